// round 10
// baseline (speedup 1.0000x reference)
#include <cuda_runtime.h>
#include <cuda_fp16.h>
#include <math.h>

// ---------------------------------------------------------------------------
// PET forward, round 10: ONE fused kernel.
//  Each block (angle-range x batch): computes H+V Gaussian blur of its batch
//  into the smem tile directly (10 column-chunks through a scratch region
//  that later becomes srow), then walks its angles' lines with 4 packed
//  walkers, (m,d) fp16 records, magic-float addressing, unroll-2 quad loop
//  with oct fp16 accumulation, fused attenuation+detector-blur+scale epilogue.
// ---------------------------------------------------------------------------

#define NB 16
#define NA 300
#define ND 300
#define TS 148
#define SMS 160
#define NBLK 9
#define CHUNK 17
#define RBLK 1024
#define MAXANG 34
#define BCC 16                     // blur chunk columns

#define TILE_BYTES (TS * SMS * 8)                  // 189440
#define HS_BYTES   (128 * (BCC + 1) * 8)           // 17408
#define VS_BYTES   (TS  * (BCC + 1) * 8)           // 20128
#define SCRATCH    (HS_BYTES + VS_BYTES)           // 37536 (srow overlaps)
#define TAB_OFF    (TILE_BYTES + SCRATCH)          // 226976
#define RAD_SMEM   (TAB_OFF + MAXANG * 32)         // 228064

// ---- packed f32x2 helpers --------------------------------------------------
#define ADD2(d,a,b)   asm("add.rn.f32x2 %0, %1, %2;" : "=l"(d) : "l"(a), "l"(b))
#define FMA2(d,a,b,c) asm("fma.rn.f32x2 %0, %1, %2, %3;" : "=l"(d) : "l"(a), "l"(b), "l"(c))

__device__ __forceinline__ unsigned long long pk2(float a, float b) {
    unsigned long long r;
    asm("mov.b64 %0, {%1, %2};" : "=l"(r) : "f"(a), "f"(b));
    return r;
}
__device__ __forceinline__ void upk_u(unsigned long long a, unsigned& lo, unsigned& hi) {
    asm("mov.b64 {%0, %1}, %2;" : "=r"(lo), "=r"(hi) : "l"(a));
}
__device__ __forceinline__ void upk_f(unsigned long long a, float& lo, float& hi) {
    asm("mov.b64 {%0, %1}, %2;" : "=f"(lo), "=f"(hi) : "l"(a));
}

#define MAGF 8388608.0f    // 2^23
#define MAGY 8388607.5f    // 2^23 - 0.5
#define KADJ (0x4B000000u * (unsigned)(SMS * 8) + 0x4B000000u * 8u)

__global__ __launch_bounds__(RBLK, 1) void radon_kernel(
        const float* __restrict__ img, const float* __restrict__ att,
        const float* __restrict__ scale, float* __restrict__ out) {
    extern __shared__ char dyn[];
    char*   tileb = dyn;
    float2* Hs    = (float2*)(dyn + TILE_BYTES);            // scratch (blur)
    float2* Vs    = (float2*)(dyn + TILE_BYTES + HS_BYTES); // scratch (blur)
    float*  srow  = (float*)(dyn + TILE_BYTES);             // later: [CHUNK][ND]
    float4* tab0  = (float4*)(dyn + TAB_OFF);               // s,c,1/s,1/c
    float4* tab1  = tab0 + MAXANG;                          // e1,e2,norm
    __shared__ float K4[9], K8[17];

    int b   = blockIdx.y;
    int blk = blockIdx.x;
    int tid = threadIdx.x;

    int aStart = (blk * NA) / NBLK;
    int aEnd   = ((blk + 1) * NA) / NBLK;
    int nAng   = aEnd - aStart;

    // ---- per-angle parameter table + blur kernels ----
    if (tid == 0) {
        const float sig_i = 1.2011224087864498f;   // 1/sqrt(ln2)
        const float sig_a = 2.4022448175728997f;   // 2/sqrt(ln2)
        float w4[9], s4 = 0.f, w8[17], s8 = 0.f;
        for (int d = -4; d <= 4; ++d) { float w = expf(-0.5f*(d/sig_i)*(d/sig_i)); w4[d+4] = w; s4 += w; }
        for (int i = 0; i < 9; ++i) K4[i] = w4[i] / s4;
        for (int d = -8; d <= 8; ++d) { float w = expf(-0.5f*(d/sig_a)*(d/sig_a)); w8[d+8] = w; s8 += w; }
        for (int i = 0; i < 17; ++i) K8[i] = w8[i] / s8;
    }
    for (int a = tid; a < nAng; a += RBLK) {
        int ang = aStart + a;
        float th  = (float)ang * 0.6020066889632107f;     // *180/299
        float rad = th * 0.017453292519943295f;
        float s, c;
        sincosf(rad, &s, &c);
        tab0[a] = make_float4(s, c, 1.0f / s, 1.0f / c);
        float bw = 2.0f * (fabsf(c) + fabsf(s));
        float q  = 0.34657359027997264f * bw * bw;
        float e1 = __expf(-q);
        float e2 = __expf(-4.0f * q);
        float norm = 1.0f / (1.0f + 2.0f * e1 + 2.0f * e2);
        tab1[a] = make_float4(e1, e2, norm, 0.f);
    }
    __syncthreads();

    // ---- in-block blur -> (m,d) records straight into smem tile ----
    {
        const float* ib = img + b * 128 * 128;
        const float* ab = att + b * 128 * 128;
        const int ncol = BCC + 1;
        uint2* tile = (uint2*)tileb;
        for (int ch = 0; ch < (TS + BCC - 1) / BCC; ++ch) {
            int c0 = ch * BCC;
            // H pass: cols [c0, c0+ncol)
            for (int idx = tid; idx < 128 * ncol; idx += RBLK) {
                int cl = idx % ncol, y = idx / ncol;
                int xc = c0 + cl - 10;
                float a0 = 0.f, a1 = 0.f;
                const float* ir = ib + y * 128;
                const float* ar = ab + y * 128;
#pragma unroll
                for (int d = -8; d <= 8; ++d) {
                    int xi = xc + d;
                    if (xi >= 0 && xi < 128) {
                        a1 += K8[d + 8] * ar[xi];
                        if (d >= -4 && d <= 4) a0 += K4[d + 4] * ir[xi];
                    }
                }
                Hs[idx] = make_float2(a0, a1);
            }
            __syncthreads();
            // V pass
            for (int idx = tid; idx < TS * ncol; idx += RBLK) {
                int cl = idx % ncol, r = idx / ncol;
                int yc = r - 10;
                float a0 = 0.f, a1 = 0.f;
#pragma unroll
                for (int d = -8; d <= 8; ++d) {
                    int yi = yc + d;
                    if (yi >= 0 && yi < 128) {
                        float2 t = Hs[yi * ncol + cl];
                        a1 += K8[d + 8] * t.y;
                        if (d >= -4 && d <= 4) a0 += K4[d + 4] * t.x;
                    }
                }
                Vs[idx] = make_float2(a0, a1 * 0.01f);
            }
            __syncthreads();
            // (m,d) records with swizzle, cols [c0, min(c0+BCC, TS))
            int nc = TS - c0 < BCC ? TS - c0 : BCC;
            for (int idx = tid; idx < TS * nc; idx += RBLK) {
                int cl = idx % nc, r = idx / nc;
                int c  = c0 + cl;
                float2 v0 = Vs[r * ncol + cl];
                float2 v1 = Vs[r * ncol + cl + 1];
                __half2 m = __floats2half2_rn(0.5f * (v0.x + v1.x), 0.5f * (v0.y + v1.y));
                __half2 d = __floats2half2_rn(v1.x - v0.x, v1.y - v0.y);
                uint2 rec;
                rec.x = *(unsigned*)&m;
                rec.y = *(unsigned*)&d;
                tile[r * SMS + (c ^ (r & 15))] = rec;
            }
            __syncthreads();
        }
    }

    const unsigned long long MAG2  = pk2(MAGF, MAGY);
    const unsigned long long NMAG2 = pk2(-MAGF, -MAGF);
    const unsigned long long NEG12 = pk2(-1.0f, -1.0f);

    auto fetch = [&](unsigned long long q, unsigned long long& fm,
                     uint2& q0, uint2& q1) {
        ADD2(fm, q, MAG2);
        unsigned xb, yb; upk_u(fm, xb, yb);
        unsigned m0 = yb & 15u;
        unsigned m1 = (yb + 1u) & 15u;
        unsigned base = yb * (SMS * 8u);
        unsigned off0 = base + ((xb ^ m0) << 3) - KADJ;
        unsigned off1 = base + ((xb ^ m1) << 3) - (KADJ - SMS * 8u);
        q0 = *(const uint2*)(tileb + off0);
        q1 = *(const uint2*)(tileb + off1);
    };
    auto interp = [&](unsigned long long q, unsigned long long fm,
                      uint2 q0, uint2 q1) -> __half2 {
        unsigned long long t, w;
        ADD2(t, fm, NMAG2);
        FMA2(w, t, NEG12, q);
        float wxf, wyf; upk_f(w, wxf, wyf);
        __half2 wpk = __floats2half2_rn(wxf, wyf);
        __half2 wx2 = __low2half2(wpk);
        __half2 wy2 = __high2half2(wpk);
        __half2 m0h = *(__half2*)&q0.x, d0h = *(__half2*)&q0.y;
        __half2 m1h = *(__half2*)&q1.x, d1h = *(__half2*)&q1.y;
        __half2 r0h = __hfma2(wx2, d0h, m0h);
        __half2 r1h = __hfma2(wx2, d1h, m1h);
        return __hfma2(wy2, __hsub2(r1h, r0h), r0h);
    };
    auto quad = [&](unsigned long long p0, unsigned long long p1,
                    unsigned long long p2, unsigned long long p3) -> __half2 {
        unsigned long long fa, fb, fc, fd;
        uint2 a0, a1, b0, b1, c0, c1, d0, d1;
        fetch(p0, fa, a0, a1);
        fetch(p1, fb, b0, b1);
        fetch(p2, fc, c0, c1);
        fetch(p3, fd, d0, d1);
        __half2 ra = interp(p0, fa, a0, a1);
        __half2 rb = interp(p1, fb, b0, b1);
        __half2 rc = interp(p2, fc, c0, c1);
        __half2 rd = interp(p3, fd, d0, d1);
        return __hadd2(__hadd2(ra, rb), __hadd2(rc, rd));
    };

    float sc = scale[b];

    for (int ang0 = aStart; ang0 < aEnd; ang0 += CHUNK) {
        int na = aEnd - ang0; if (na > CHUNK) na = CHUNK;
        int items = na * ND;
        int tabBase = ang0 - aStart;

        for (int it = tid; it < items; it += RBLK) {
            int al = it / ND;
            int j  = it - al * ND;
            float4 T = tab0[tabBase + al];
            float s = T.x, c = T.y, is = T.z, ic = T.w;
            float u  = (float)j - 149.5f;
            float bx = fmaf(c,  u, fmaf(-149.5f, s, 73.5f));
            float by = fmaf(-s, u, fmaf(-149.5f, c, 73.5f));

            const float LO = 0.999f, HI = 146.001f;
            float rxa = (LO - bx) * is, rxb = (HI - bx) * is;
            float rya = (LO - by) * ic, ryb = (HI - by) * ic;
            float t0 = fmaxf(0.f,   fmaxf(fminf(rxa, rxb), fminf(rya, ryb)));
            float t1 = fminf(299.f, fminf(fmaxf(rxa, rxb), fmaxf(rya, ryb)));

            float S = 0.f, A = 0.f;
            if (t0 <= t1) {
                int i0 = (int)ceilf(t0);
                int i1 = (int)floorf(t1);
                int n  = i1 - i0 + 1;
                float lx0 = fmaf(s, (float)i0, bx - 0.5f);
                float ly0 = fmaf(c, (float)i0, by);
                unsigned long long st1 = pk2(s, c);
                unsigned long long st4 = pk2(4.f * s, 4.f * c);
                unsigned long long p0 = pk2(lx0, ly0);
                unsigned long long p1, p2, p3;
                ADD2(p1, p0, st1);
                ADD2(p2, p1, st1);
                ADD2(p3, p2, st1);
                int k = 0;
#pragma unroll 1
                for (; k + 7 < n; k += 8) {      // oct: two quads, one convert
                    __half2 qa = quad(p0, p1, p2, p3);
                    ADD2(p0, p0, st4);
                    ADD2(p1, p1, st4);
                    ADD2(p2, p2, st4);
                    ADD2(p3, p3, st4);
                    __half2 qb = quad(p0, p1, p2, p3);
                    ADD2(p0, p0, st4);
                    ADD2(p1, p1, st4);
                    ADD2(p2, p2, st4);
                    ADD2(p3, p3, st4);
                    float2 f = __half22float2(__hadd2(qa, qb));
                    S += f.x; A += f.y;
                }
                if (k + 3 < n) {                 // leftover quad
                    float2 f = __half22float2(quad(p0, p1, p2, p3));
                    S += f.x; A += f.y;
                    ADD2(p0, p0, st4);
                    k += 4;
                }
#pragma unroll 1
                for (; k < n; ++k) {             // scalar tail (<=3)
                    unsigned long long fa; uint2 a0, a1;
                    fetch(p0, fa, a0, a1);
                    float2 f = __half22float2(interp(p0, fa, a0, a1));
                    S += f.x; A += f.y;
                    ADD2(p0, p0, st1);
                }
            }
            srow[al * ND + j] = S * __expf(-2.0f * A);
        }
        __syncthreads();

        float* o_base = out + (b * NA + ang0) * ND;
        for (int it = tid; it < items; it += RBLK) {
            int al = it / ND;
            int j  = it - al * ND;
            float4 E = tab1[tabBase + al];
            float e1 = E.x, e2 = E.y, norm = E.z;
            const float* row = srow + al * ND;
            int jm2 = j - 2; jm2 = jm2 < 0 ? -jm2 : jm2;
            int jm1 = j - 1; jm1 = jm1 < 0 ? -jm1 : jm1;
            int jp1 = j + 1; jp1 = jp1 > ND - 1 ? 2 * (ND - 1) - jp1 : jp1;
            int jp2 = j + 2; jp2 = jp2 > ND - 1 ? 2 * (ND - 1) - jp2 : jp2;
            float acc = row[j]
                      + e1 * (row[jm1] + row[jp1])
                      + e2 * (row[jm2] + row[jp2]);
            o_base[al * ND + j] = acc * norm * sc;
        }
        __syncthreads();
    }
}

// ---------------------------------------------------------------------------
extern "C" void kernel_launch(void* const* d_in, const int* in_sizes, int n_in,
                              void* d_out, int out_size) {
    const float* img   = (const float*)d_in[0];
    const float* att   = (const float*)d_in[1];
    const float* scale = (const float*)d_in[2];
    float* out = (float*)d_out;
    (void)in_sizes; (void)n_in; (void)out_size;

    cudaFuncSetAttribute(radon_kernel, cudaFuncAttributeMaxDynamicSharedMemorySize,
                         RAD_SMEM);
    radon_kernel<<<dim3(NBLK, NB), RBLK, RAD_SMEM>>>(img, att, scale, out);
}

// round 11
// speedup vs baseline: 1.3217x; 1.3217x over previous
#include <cuda_runtime.h>
#include <cuda_fp16.h>
#include <math.h>

// ---------------------------------------------------------------------------
// PET forward, round 11 (= round 9 structure + oct accumulation):
//  - prep (128 blocks, column-split with halo): H+V blur, (m,d) fp16 records.
//  - radon: one-wave grid (9 x 16), tile staged once, per-angle param table.
//    4 packed-f32x2 walkers, batched fetches (8 LDS.64 in flight), (m,d)
//    HFMA2 bilinear, unroll-2 quad loop with oct fp16 accumulation,
//    fused attenuation + detector-blur + scale epilogue.
// ---------------------------------------------------------------------------

#define NB 16
#define NA 300
#define ND 300
#define TS 148
#define SMS 160
#define NBLK 9
#define CHUNK 17
#define RBLK 1024
#define NSPLIT 8
#define CPB 19
#define MAXANG 34

#define TILE_BYTES (TS * SMS * 8)
#define SROW_BYTES (CHUNK * ND * 4)
#define RAD_SMEM   (TILE_BYTES + SROW_BYTES + MAXANG * 32)

__device__ uint2 g_tile[NB][TS][TS];

// ---- packed f32x2 helpers --------------------------------------------------
#define ADD2(d,a,b)   asm("add.rn.f32x2 %0, %1, %2;" : "=l"(d) : "l"(a), "l"(b))
#define FMA2(d,a,b,c) asm("fma.rn.f32x2 %0, %1, %2, %3;" : "=l"(d) : "l"(a), "l"(b), "l"(c))

__device__ __forceinline__ unsigned long long pk2(float a, float b) {
    unsigned long long r;
    asm("mov.b64 %0, {%1, %2};" : "=l"(r) : "f"(a), "f"(b));
    return r;
}
__device__ __forceinline__ void upk_u(unsigned long long a, unsigned& lo, unsigned& hi) {
    asm("mov.b64 {%0, %1}, %2;" : "=r"(lo), "=r"(hi) : "l"(a));
}
__device__ __forceinline__ void upk_f(unsigned long long a, float& lo, float& hi) {
    asm("mov.b64 {%0, %1}, %2;" : "=f"(lo), "=f"(hi) : "l"(a));
}

// ---------------------------------------------------------------------------
__global__ __launch_bounds__(512, 2) void prep_kernel(
        const float* __restrict__ img, const float* __restrict__ att) {
    extern __shared__ float2 dynp[];
    float2* Hs = dynp;                    // [128][CPB+1]
    float2* Vs = dynp + 128 * (CPB + 1);  // [TS][CPB+1]
    __shared__ float K4[9], K8[17];
    int b  = blockIdx.y;
    int c0 = blockIdx.x * CPB;
    int tid = threadIdx.x;
    int ncol = CPB + 1;

    if (tid == 0) {
        const float sig_i = 1.2011224087864498f;
        const float sig_a = 2.4022448175728997f;
        float w4[9], s4 = 0.f, w8[17], s8 = 0.f;
        for (int d = -4; d <= 4; ++d) { float w = expf(-0.5f*(d/sig_i)*(d/sig_i)); w4[d+4] = w; s4 += w; }
        for (int i = 0; i < 9; ++i) K4[i] = w4[i] / s4;
        for (int d = -8; d <= 8; ++d) { float w = expf(-0.5f*(d/sig_a)*(d/sig_a)); w8[d+8] = w; s8 += w; }
        for (int i = 0; i < 17; ++i) K8[i] = w8[i] / s8;
    }
    __syncthreads();

    const float* ib = img + b * 128 * 128;
    const float* ab = att + b * 128 * 128;
    for (int idx = tid; idx < 128 * ncol; idx += blockDim.x) {
        int cl = idx % ncol, y = idx / ncol;
        int xc = c0 + cl - 10;
        float a0 = 0.f, a1 = 0.f;
        const float* ir = ib + y * 128;
        const float* ar = ab + y * 128;
#pragma unroll
        for (int d = -8; d <= 8; ++d) {
            int xi = xc + d;
            if (xi >= 0 && xi < 128) {
                a1 += K8[d + 8] * ar[xi];
                if (d >= -4 && d <= 4) a0 += K4[d + 4] * ir[xi];
            }
        }
        Hs[idx] = make_float2(a0, a1);
    }
    __syncthreads();

    for (int idx = tid; idx < TS * ncol; idx += blockDim.x) {
        int cl = idx % ncol, r = idx / ncol;
        int yc = r - 10;
        float a0 = 0.f, a1 = 0.f;
#pragma unroll
        for (int d = -8; d <= 8; ++d) {
            int yi = yc + d;
            if (yi >= 0 && yi < 128) {
                float2 t = Hs[yi * ncol + cl];
                a1 += K8[d + 8] * t.y;
                if (d >= -4 && d <= 4) a0 += K4[d + 4] * t.x;
            }
        }
        Vs[idx] = make_float2(a0, a1 * 0.01f);
    }
    __syncthreads();

    uint2* gt = (uint2*)&g_tile[b][0][0];
    for (int idx = tid; idx < TS * CPB; idx += blockDim.x) {
        int cl = idx % CPB, r = idx / CPB;
        int c  = c0 + cl;
        if (c >= TS) continue;
        float2 v0 = Vs[r * ncol + cl];
        float2 v1 = Vs[r * ncol + cl + 1];
        __half2 m = __floats2half2_rn(0.5f * (v0.x + v1.x), 0.5f * (v0.y + v1.y));
        __half2 d = __floats2half2_rn(v1.x - v0.x, v1.y - v0.y);
        uint2 rec;
        rec.x = *(unsigned*)&m;
        rec.y = *(unsigned*)&d;
        gt[r * TS + c] = rec;
    }
}

// ---------------------------------------------------------------------------
#define MAGF 8388608.0f    // 2^23
#define MAGY 8388607.5f    // 2^23 - 0.5
#define KADJ (0x4B000000u * (unsigned)(SMS * 8) + 0x4B000000u * 8u)

__global__ __launch_bounds__(RBLK, 1) void radon_kernel(
        const float* __restrict__ scale, float* __restrict__ out) {
    extern __shared__ char dyn[];
    char*   tileb = dyn;
    float*  srow  = (float*)(dyn + TILE_BYTES);                 // [CHUNK][ND]
    float4* tab0  = (float4*)(dyn + TILE_BYTES + SROW_BYTES);   // s,c,1/s,1/c
    float4* tab1  = tab0 + MAXANG;                              // e1,e2,norm

    int b   = blockIdx.y;
    int blk = blockIdx.x;
    int tid = threadIdx.x;

    int aStart = (blk * NA) / NBLK;
    int aEnd   = ((blk + 1) * NA) / NBLK;
    int nAng   = aEnd - aStart;

    for (int a = tid; a < nAng; a += RBLK) {
        int ang = aStart + a;
        float th  = (float)ang * 0.6020066889632107f;
        float rad = th * 0.017453292519943295f;
        float s, c;
        sincosf(rad, &s, &c);
        tab0[a] = make_float4(s, c, 1.0f / s, 1.0f / c);
        float bw = 2.0f * (fabsf(c) + fabsf(s));
        float q  = 0.34657359027997264f * bw * bw;
        float e1 = __expf(-q);
        float e2 = __expf(-4.0f * q);
        float norm = 1.0f / (1.0f + 2.0f * e1 + 2.0f * e2);
        tab1[a] = make_float4(e1, e2, norm, 0.f);
    }

    {
        uint2* tile = (uint2*)tileb;
        const uint2* gt = &g_tile[b][0][0];
        for (int i = tid; i < TS * TS; i += RBLK) {
            int y = i / TS, x = i - y * TS;
            tile[y * SMS + (x ^ (y & 15))] = gt[i];
        }
    }
    __syncthreads();

    const unsigned long long MAG2  = pk2(MAGF, MAGY);
    const unsigned long long NMAG2 = pk2(-MAGF, -MAGF);
    const unsigned long long NEG12 = pk2(-1.0f, -1.0f);

    auto fetch = [&](unsigned long long q, unsigned long long& fm,
                     uint2& q0, uint2& q1) {
        ADD2(fm, q, MAG2);
        unsigned xb, yb; upk_u(fm, xb, yb);
        unsigned m0 = yb & 15u;
        unsigned m1 = (yb + 1u) & 15u;
        unsigned base = yb * (SMS * 8u);
        unsigned off0 = base + ((xb ^ m0) << 3) - KADJ;
        unsigned off1 = base + ((xb ^ m1) << 3) - (KADJ - SMS * 8u);
        q0 = *(const uint2*)(tileb + off0);
        q1 = *(const uint2*)(tileb + off1);
    };
    auto interp = [&](unsigned long long q, unsigned long long fm,
                      uint2 q0, uint2 q1) -> __half2 {
        unsigned long long t, w;
        ADD2(t, fm, NMAG2);
        FMA2(w, t, NEG12, q);
        float wxf, wyf; upk_f(w, wxf, wyf);
        __half2 wpk = __floats2half2_rn(wxf, wyf);
        __half2 wx2 = __low2half2(wpk);
        __half2 wy2 = __high2half2(wpk);
        __half2 m0h = *(__half2*)&q0.x, d0h = *(__half2*)&q0.y;
        __half2 m1h = *(__half2*)&q1.x, d1h = *(__half2*)&q1.y;
        __half2 r0h = __hfma2(wx2, d0h, m0h);
        __half2 r1h = __hfma2(wx2, d1h, m1h);
        return __hfma2(wy2, __hsub2(r1h, r0h), r0h);
    };
    auto quad = [&](unsigned long long p0, unsigned long long p1,
                    unsigned long long p2, unsigned long long p3) -> __half2 {
        unsigned long long fa, fb, fc, fd;
        uint2 a0, a1, b0, b1, c0, c1, d0, d1;
        fetch(p0, fa, a0, a1);
        fetch(p1, fb, b0, b1);
        fetch(p2, fc, c0, c1);
        fetch(p3, fd, d0, d1);
        __half2 ra = interp(p0, fa, a0, a1);
        __half2 rb = interp(p1, fb, b0, b1);
        __half2 rc = interp(p2, fc, c0, c1);
        __half2 rd = interp(p3, fd, d0, d1);
        return __hadd2(__hadd2(ra, rb), __hadd2(rc, rd));
    };

    float sc = scale[b];

    for (int ang0 = aStart; ang0 < aEnd; ang0 += CHUNK) {
        int na = aEnd - ang0; if (na > CHUNK) na = CHUNK;
        int items = na * ND;
        int tabBase = ang0 - aStart;

        for (int it = tid; it < items; it += RBLK) {
            int al = it / ND;
            int j  = it - al * ND;
            float4 T = tab0[tabBase + al];
            float s = T.x, c = T.y, is = T.z, ic = T.w;
            float u  = (float)j - 149.5f;
            float bx = fmaf(c,  u, fmaf(-149.5f, s, 73.5f));
            float by = fmaf(-s, u, fmaf(-149.5f, c, 73.5f));

            const float LO = 0.999f, HI = 146.001f;
            float rxa = (LO - bx) * is, rxb = (HI - bx) * is;
            float rya = (LO - by) * ic, ryb = (HI - by) * ic;
            float t0 = fmaxf(0.f,   fmaxf(fminf(rxa, rxb), fminf(rya, ryb)));
            float t1 = fminf(299.f, fminf(fmaxf(rxa, rxb), fmaxf(rya, ryb)));

            float S = 0.f, A = 0.f;
            if (t0 <= t1) {
                int i0 = (int)ceilf(t0);
                int i1 = (int)floorf(t1);
                int n  = i1 - i0 + 1;
                float lx0 = fmaf(s, (float)i0, bx - 0.5f);
                float ly0 = fmaf(c, (float)i0, by);
                unsigned long long st1 = pk2(s, c);
                unsigned long long st4 = pk2(4.f * s, 4.f * c);
                unsigned long long p0 = pk2(lx0, ly0);
                unsigned long long p1, p2, p3;
                ADD2(p1, p0, st1);
                ADD2(p2, p1, st1);
                ADD2(p3, p2, st1);
                int k = 0;
#pragma unroll 1
                for (; k + 7 < n; k += 8) {      // oct: two quads, one convert
                    __half2 qa = quad(p0, p1, p2, p3);
                    ADD2(p0, p0, st4);
                    ADD2(p1, p1, st4);
                    ADD2(p2, p2, st4);
                    ADD2(p3, p3, st4);
                    __half2 qb = quad(p0, p1, p2, p3);
                    ADD2(p0, p0, st4);
                    ADD2(p1, p1, st4);
                    ADD2(p2, p2, st4);
                    ADD2(p3, p3, st4);
                    float2 f = __half22float2(__hadd2(qa, qb));
                    S += f.x; A += f.y;
                }
                if (k + 3 < n) {                 // leftover quad
                    float2 f = __half22float2(quad(p0, p1, p2, p3));
                    S += f.x; A += f.y;
                    ADD2(p0, p0, st4);
                    k += 4;
                }
#pragma unroll 1
                for (; k < n; ++k) {             // scalar tail (<=3)
                    unsigned long long fa; uint2 a0, a1;
                    fetch(p0, fa, a0, a1);
                    float2 f = __half22float2(interp(p0, fa, a0, a1));
                    S += f.x; A += f.y;
                    ADD2(p0, p0, st1);
                }
            }
            srow[al * ND + j] = S * __expf(-2.0f * A);
        }
        __syncthreads();

        float* o_base = out + (b * NA + ang0) * ND;
        for (int it = tid; it < items; it += RBLK) {
            int al = it / ND;
            int j  = it - al * ND;
            float4 E = tab1[tabBase + al];
            float e1 = E.x, e2 = E.y, norm = E.z;
            const float* row = srow + al * ND;
            int jm2 = j - 2; jm2 = jm2 < 0 ? -jm2 : jm2;
            int jm1 = j - 1; jm1 = jm1 < 0 ? -jm1 : jm1;
            int jp1 = j + 1; jp1 = jp1 > ND - 1 ? 2 * (ND - 1) - jp1 : jp1;
            int jp2 = j + 2; jp2 = jp2 > ND - 1 ? 2 * (ND - 1) - jp2 : jp2;
            float acc = row[j]
                      + e1 * (row[jm1] + row[jp1])
                      + e2 * (row[jm2] + row[jp2]);
            o_base[al * ND + j] = acc * norm * sc;
        }
        __syncthreads();
    }
}

// ---------------------------------------------------------------------------
extern "C" void kernel_launch(void* const* d_in, const int* in_sizes, int n_in,
                              void* d_out, int out_size) {
    const float* img   = (const float*)d_in[0];
    const float* att   = (const float*)d_in[1];
    const float* scale = (const float*)d_in[2];
    float* out = (float*)d_out;
    (void)in_sizes; (void)n_in; (void)out_size;

    int prep_smem = (128 + TS) * (CPB + 1) * (int)sizeof(float2);
    cudaFuncSetAttribute(prep_kernel,  cudaFuncAttributeMaxDynamicSharedMemorySize,
                         prep_smem);
    cudaFuncSetAttribute(radon_kernel, cudaFuncAttributeMaxDynamicSharedMemorySize,
                         RAD_SMEM);

    prep_kernel<<<dim3(NSPLIT, NB), 512, prep_smem>>>(img, att);
    radon_kernel<<<dim3(NBLK, NB), RBLK, RAD_SMEM>>>(scale, out);
}